// round 6
// baseline (speedup 1.0000x reference)
#include <cuda_runtime.h>
#include <mma.h>
#include <cstdint>

using namespace nvcuda;

#define Bsz 128
#define Tt  256
#define Hh  1024
#define Vv  4096
#define BH  (Bsz*Hh)

#define CHF  4224          // floats per A-chunk: 32 k-rows * 132 (128 b + 4 pad)
#define CHB  16896         // bytes per A-chunk
#define TCH  32            // chunks per K=1024
#define WTF  1152          // floats per 32n x 36k weight tile chunk (4608 B)
#define WFCF 4608          // floats per 128n x 36k FC weight tile chunk (18432 B)

// ---- device scratch (static globals; no allocation) ----
__device__ float g_h0T[2][TCH*CHF];      // h0 state, transposed chunked, double buffer
__device__ float g_h1T[Tt][TCH*CHF];     // h1 history, transposed chunked (~138 MB)
__device__ float g_xT[Tt*Bsz];           // x transposed [t][b]
__device__ float g_Wt0[32*32*WTF];       // Whh0 tiled   [nt32][c32][32n][36k]
__device__ float g_Wt1[32*64*WTF];       // [Wih1;Whh1]  [nt32][c64][32n][36k]
__device__ float g_WtF[32*32*WFCF];      // Wfc tiled    [vt32][c32][128n][36k]

// ---- ptx helpers ----
__device__ __forceinline__ uint32_t s2u(const void* p){
  return (uint32_t)__cvta_generic_to_shared(p);
}
__device__ __forceinline__ void mbar_init(uint32_t mb){
  asm volatile("mbarrier.init.shared::cta.b64 [%0], 1;" :: "r"(mb));
}
__device__ __forceinline__ void mbar_expect(uint32_t mb, uint32_t tx){
  asm volatile("mbarrier.arrive.expect_tx.shared::cta.b64 _, [%0], %1;" :: "r"(mb), "r"(tx) : "memory");
}
__device__ __forceinline__ void bulk_ld(uint32_t dst, const void* src, uint32_t bytes, uint32_t mb){
  asm volatile("cp.async.bulk.shared::cta.global.mbarrier::complete_tx::bytes [%0], [%1], %2, [%3];"
               :: "r"(dst), "l"(src), "r"(bytes), "r"(mb) : "memory");
}
__device__ __forceinline__ void mbar_wait(uint32_t mb, uint32_t ph){
  uint32_t done = 0;
  do {
    asm volatile("{\n\t.reg .pred p;\n\t"
                 "mbarrier.try_wait.parity.shared::cta.b64 p, [%1], %2;\n\t"
                 "selp.b32 %0,1,0,p;\n\t}"
                 : "=r"(done) : "r"(mb), "r"(ph) : "memory");
  } while(!done);
}

// ---------------------------------------------------------------------------
// Prologue: re-tile weights + transpose x into bulk-copy-friendly layouts.
// Runs every launch (deterministic). ~66 MB traffic ≈ 20-30 us.
// ---------------------------------------------------------------------------
#define N_WT0 (32*32*WTF)
#define N_WT1 (32*64*WTF)
#define N_WTF (32*32*WFCF)
#define N_XT  (Tt*Bsz)
#define N_TOT (N_WT0+N_WT1+N_WTF+N_XT)

__global__ void pretile(const float* __restrict__ x,
                        const float* __restrict__ Whh0,
                        const float* __restrict__ Wih1,
                        const float* __restrict__ Whh1,
                        const float* __restrict__ Wfc)
{
  for (long long i = (long long)blockIdx.x*blockDim.x + threadIdx.x; i < N_TOT;
       i += (long long)gridDim.x*blockDim.x){
    long long j = i;
    if (j < N_WT0){
      int nt = (int)(j/(32*WTF)); int r = (int)(j%(32*WTF));
      int c = r/WTF; int q = r%WTF; int nl = q/36, kk = q%36;
      int n = nt*32+nl;
      g_Wt0[j] = (kk<32) ? Whh0[n*Hh + c*32 + kk] : 0.f;
      continue;
    }
    j -= N_WT0;
    if (j < N_WT1){
      int nt = (int)(j/(64*WTF)); int r = (int)(j%(64*WTF));
      int c = r/WTF; int q = r%WTF; int nl = q/36, kk = q%36;
      int n = nt*32+nl;
      float v = 0.f;
      if (kk<32) v = (c<32) ? Wih1[n*Hh + c*32 + kk] : Whh1[n*Hh + (c-32)*32 + kk];
      g_Wt1[(long long)(nt*64 + c)*WTF + q] = v;
      continue;
    }
    j -= N_WT1;
    if (j < N_WTF){
      int vt = (int)(j/(32*WFCF)); int r = (int)(j%(32*WFCF));
      int c = r/WFCF; int q = r%WFCF; int nl = q/36, kk = q%36;
      int n = vt*128+nl;
      g_WtF[(long long)(vt*32 + c)*WFCF + q] = (kk<32) ? Wfc[(size_t)n*Hh + c*32 + kk] : 0.f;
      continue;
    }
    j -= N_WTF;
    { int t = (int)(j/Bsz), b = (int)(j%Bsz); g_xT[t*Bsz + b] = x[(size_t)b*Tt + t]; }
  }
}

// ---------------------------------------------------------------------------
// Recurrence step (pipelined across launches). Launch k in 0..T:
//  blocks 0..31  (k<T):  h0[k]   = tanh(x_k*Wih0 + h0[k-1]@Whh0^T + b0)
//  blocks 32..63 (k>=1): h1[k-1] = tanh(h0[k-1]@Wih1^T + h1[k-2]@Whh1^T + b1)
// CTA: BM=128 (batch), BN=32, K via bulk-copied 32-wide chunks, 4-stage mbar pipe.
// ---------------------------------------------------------------------------
#define RS_STGF 5376            // stage floats: 4224 A + 1152 B
#define RS_SMEM (4*RS_STGF*4)   // 86016 B

__global__ void __launch_bounds__(256) rnn_step(
  const float* __restrict__ Wih0,
  const float* __restrict__ bih0, const float* __restrict__ bhh0,
  const float* __restrict__ bih1, const float* __restrict__ bhh1,
  int k)
{
  extern __shared__ __align__(16) float sm[];
  __shared__ __align__(8) uint64_t mbar_s[4];
  const int tid = threadIdx.x, w = tid>>5;
  const bool is1 = (blockIdx.x >= 32);
  if (!is1 && k==Tt) return;
  if ( is1 && k==0 ) return;
  const int nt = is1 ? (int)blockIdx.x-32 : (int)blockIdx.x;
  const int n0 = nt*32;

  const float* h0prev  = g_h0T[(k+1)&1];
  const float* h1prev2 = (k>=2) ? g_h1T[k-2] : g_h1T[0];
  const int nc = is1 ? ((k>=2)?64:32) : ((k>=1)?32:0);

  wmma::fragment<wmma::accumulator,16,16,8,float> c0,c1;
  wmma::fill_fragment(c0,0.f); wmma::fill_fragment(c1,0.f);

  if (nc > 0){
    const uint32_t smb = s2u(sm);
    const uint32_t mbb = s2u(mbar_s);
    if (tid==0){
      #pragma unroll
      for (int s=0;s<4;s++) mbar_init(mbb+8*s);
      asm volatile("fence.proxy.async.shared::cta;" ::: "memory");
    }
    __syncthreads();

    auto issue = [&](int c){
      const int s = c&3;
      const uint32_t mb = mbb + 8*s;
      mbar_expect(mb, CHB + 4608);
      const float* asrc; const float* bsrc;
      if (!is1){ asrc = h0prev + c*CHF;  bsrc = g_Wt0 + (nt*32 + c)*WTF; }
      else     { asrc = (c<32) ? h0prev + c*CHF : h1prev2 + (c-32)*CHF;
                 bsrc = g_Wt1 + (nt*64 + c)*WTF; }
      const uint32_t da = smb + (uint32_t)s*RS_STGF*4;
      bulk_ld(da,        asrc, CHB,  mb);
      bulk_ld(da+CHB,    bsrc, 4608, mb);
    };
    if (tid==0){ const int pre = nc<4?nc:4; for (int c=0;c<pre;c++) issue(c); }

    for (int c=0;c<nc;c++){
      mbar_wait(mbb + 8*(c&3), (uint32_t)((c>>2)&1));
      const float* a_s = sm + (c&3)*RS_STGF;
      const float* b_s = a_s + CHF;
      #pragma unroll
      for (int kk=0;kk<4;kk++){
        wmma::fragment<wmma::matrix_a,16,16,8,wmma::precision::tf32,wmma::col_major> af;
        wmma::load_matrix_sync(af, a_s + kk*8*132 + w*16, 132);
        #pragma unroll
        for (int e=0;e<af.num_elements;e++) af.x[e]=wmma::__float_to_tf32(af.x[e]);
        wmma::fragment<wmma::matrix_b,16,16,8,wmma::precision::tf32,wmma::col_major> bf;
        wmma::load_matrix_sync(bf, b_s + kk*8, 36);
        #pragma unroll
        for (int e=0;e<bf.num_elements;e++) bf.x[e]=wmma::__float_to_tf32(bf.x[e]);
        wmma::mma_sync(c0, af, bf, c0);
        wmma::load_matrix_sync(bf, b_s + 16*36 + kk*8, 36);
        #pragma unroll
        for (int e=0;e<bf.num_elements;e++) bf.x[e]=wmma::__float_to_tf32(bf.x[e]);
        wmma::mma_sync(c1, af, bf, c1);
      }
      __syncthreads();
      if (tid==0 && c+4<nc) issue(c+4);
    }
  }

  // epilogue: stage 128x32 tile [128][36], bias(+input), tanh, write transposed
  float* stg = sm;
  wmma::store_matrix_sync(stg + (w*16)*36,      c0, 36, wmma::mem_row_major);
  wmma::store_matrix_sync(stg + (w*16)*36 + 16, c1, 36, wmma::mem_row_major);
  __syncthreads();

  if (!is1){
    float* dst = g_h0T[k&1];
    #pragma unroll
    for (int i=0;i<16;i++){
      int f = tid + i*256;
      int nl = f>>7, b = f&127, n = n0+nl;
      float v = stg[b*36+nl] + g_xT[k*Bsz+b]*Wih0[n] + bih0[n] + bhh0[n];
      dst[(n>>5)*CHF + (n&31)*132 + b] = tanhf(v);
    }
  } else {
    float* dst = g_h1T[k-1];
    #pragma unroll
    for (int i=0;i<16;i++){
      int f = tid + i*256;
      int nl = f>>7, b = f&127, n = n0+nl;
      float v = stg[b*36+nl] + bih1[n] + bhh1[n];
      dst[(n>>5)*CHF + (n&31)*132 + b] = tanhf(v);
    }
  }
}

// ---------------------------------------------------------------------------
// FC: out[b,t,v] = h1[t][b,:] @ Wfc[v,:] + bfc[v]
// CTA tile: BM=256 (two timesteps) x BN=128, 3-stage bulk pipeline.
// Grid (32 vtiles, 128 mtiles).
// ---------------------------------------------------------------------------
#define FC_STGF 13056          // 2*4224 A + 4608 B floats
#define FC_SMEM (3*FC_STGF*4)  // 156672 B

__global__ void __launch_bounds__(256) fc2(const float* __restrict__ bfc,
                                           float* __restrict__ out)
{
  extern __shared__ __align__(16) float sm[];
  __shared__ __align__(8) uint64_t mbar_s[3];
  const int tid = threadIdx.x, w = tid>>5, wm = w&3, wn = w>>2;
  const int vt = blockIdx.x, mt = blockIdx.y;
  const float* A0 = g_h1T[2*mt];
  const float* A1 = g_h1T[2*mt+1];

  wmma::fragment<wmma::accumulator,16,16,8,float> cf[4][4];
  #pragma unroll
  for (int i=0;i<4;i++)
    #pragma unroll
    for (int j=0;j<4;j++) wmma::fill_fragment(cf[i][j],0.f);

  const uint32_t smb = s2u(sm);
  const uint32_t mbb = s2u(mbar_s);
  if (tid==0){
    #pragma unroll
    for (int s=0;s<3;s++) mbar_init(mbb+8*s);
    asm volatile("fence.proxy.async.shared::cta;" ::: "memory");
  }
  __syncthreads();

  auto issue = [&](int c){
    const int s = c%3;
    const uint32_t mb = mbb + 8*s;
    mbar_expect(mb, 2*CHB + 18432);
    const uint32_t da = smb + (uint32_t)s*FC_STGF*4;
    bulk_ld(da,         A0 + c*CHF, CHB, mb);
    bulk_ld(da+CHB,     A1 + c*CHF, CHB, mb);
    bulk_ld(da+2*CHB,   g_WtF + (size_t)(vt*32 + c)*WFCF, 18432, mb);
  };
  if (tid==0){ for (int c=0;c<3;c++) issue(c); }

  for (int c=0;c<32;c++){
    mbar_wait(mbb + 8*(c%3), (uint32_t)((c/3)&1));
    const float* st = sm + (c%3)*FC_STGF;
    const float* b_s = st + 2*CHF;
    #pragma unroll
    for (int kk=0;kk<4;kk++){
      wmma::fragment<wmma::matrix_a,16,16,8,wmma::precision::tf32,wmma::col_major> af[4];
      #pragma unroll
      for (int i=0;i<4;i++){
        int m = wm*64 + i*16;
        const float* ab = (m>=128) ? (st+CHF) : st;
        wmma::load_matrix_sync(af[i], ab + kk*8*132 + (m&127), 132);
        #pragma unroll
        for (int e=0;e<af[i].num_elements;e++) af[i].x[e]=wmma::__float_to_tf32(af[i].x[e]);
      }
      #pragma unroll
      for (int j=0;j<4;j++){
        wmma::fragment<wmma::matrix_b,16,16,8,wmma::precision::tf32,wmma::col_major> bf;
        wmma::load_matrix_sync(bf, b_s + (wn*64 + j*16)*36 + kk*8, 36);
        #pragma unroll
        for (int e=0;e<bf.num_elements;e++) bf.x[e]=wmma::__float_to_tf32(bf.x[e]);
        #pragma unroll
        for (int i=0;i<4;i++) wmma::mma_sync(cf[i][j], af[i], bf, cf[i][j]);
      }
    }
    __syncthreads();
    if (tid==0 && c+3<32) issue(c+3);
  }

  // epilogue: two 256x64 halves via smem [256][68], bias, float4 stores
  float* stg = sm;
  #pragma unroll
  for (int h=0; h<2; h++){
    if (wn==h){
      #pragma unroll
      for (int i=0;i<4;i++)
        #pragma unroll
        for (int j=0;j<4;j++)
          wmma::store_matrix_sync(stg + (wm*64+i*16)*68 + j*16, cf[i][j], 68, wmma::mem_row_major);
    }
    __syncthreads();
    #pragma unroll
    for (int i=0;i<16;i++){
      int f = tid + i*256;
      int r = f>>4, c4 = f&15;
      int n = vt*128 + h*64 + c4*4;
      float4 v  = *(float4*)(stg + r*68 + c4*4);
      float4 bb = *(const float4*)(bfc + n);
      v.x+=bb.x; v.y+=bb.y; v.z+=bb.z; v.w+=bb.w;
      int b = r&127, t = 2*mt + (r>>7);
      *(float4*)(out + ((size_t)b*Tt + t)*(size_t)Vv + n) = v;
    }
    __syncthreads();
  }
}

// Final hidden states -> out tail [2, B, H] (de-transpose from chunked layout)
__global__ void states_kernel(float* __restrict__ out){
  int i = blockIdx.x*blockDim.x + threadIdx.x;
  if (i >= 2*BH) return;
  const size_t BTV = (size_t)Bsz*Tt*Vv;
  int layer = i >= BH;
  int j = i - layer*BH;
  int b = j>>10, n = j&1023;
  const float* src = layer ? g_h1T[Tt-1] : g_h0T[(Tt-1)&1];
  out[BTV + i] = src[(n>>5)*CHF + (n&31)*132 + b];
}

extern "C" void kernel_launch(void* const* d_in, const int* in_sizes, int n_in,
                              void* d_out, int out_size) {
  const float* x    = (const float*)d_in[0];
  const float* Wih0 = (const float*)d_in[1];
  const float* Whh0 = (const float*)d_in[2];
  const float* bih0 = (const float*)d_in[3];
  const float* bhh0 = (const float*)d_in[4];
  const float* Wih1 = (const float*)d_in[5];
  const float* Whh1 = (const float*)d_in[6];
  const float* bih1 = (const float*)d_in[7];
  const float* bhh1 = (const float*)d_in[8];
  const float* Wfc  = (const float*)d_in[9];
  const float* bfc  = (const float*)d_in[10];
  float* out = (float*)d_out;

  cudaFuncSetAttribute(rnn_step, cudaFuncAttributeMaxDynamicSharedMemorySize, RS_SMEM);
  cudaFuncSetAttribute(fc2,      cudaFuncAttributeMaxDynamicSharedMemorySize, FC_SMEM);

  // 1) re-tile weights + x into bulk-friendly layouts
  pretile<<<4096, 256>>>(x, Whh0, Wih1, Whh1, Wfc);

  // 2) pipelined recurrence: launch k computes h0[k] and h1[k-1]
  for (int k = 0; k <= Tt; ++k)
    rnn_step<<<64, 256, RS_SMEM>>>(Wih0, bih0, bhh0, bih1, bhh1, k);

  // 3) batched trailing linear
  fc2<<<dim3(32,128), 256, FC_SMEM>>>(bfc, out);

  // 4) final states tail
  long long need = (long long)Bsz*Tt*Vv + 2LL*BH;
  if ((long long)out_size >= need)
    states_kernel<<<(2*BH + 255)/256, 256>>>(out);
}

// round 7
// speedup vs baseline: 1.0021x; 1.0021x over previous
#include <cuda_runtime.h>
#include <mma.h>
#include <cstdint>

using namespace nvcuda;

#define Bsz 128
#define Tt  256
#define Hh  1024
#define Vv  4096
#define BH  (Bsz*Hh)

#define CHF  4224          // floats per A-chunk: 32 k-rows * 132 (128 b + 4 pad)
#define CHB  16896         // bytes per A-chunk
#define TCH  32            // chunks per K=1024
#define WTF  1152          // floats per 32n x 36k weight tile chunk (4608 B)
#define WFCF 4608          // floats per 128n x 36k FC weight tile chunk (18432 B)

// ---- device scratch (static globals; no allocation) ----
__device__ float g_h0T[2][TCH*CHF];      // h0 state, transposed chunked, double buffer
__device__ float g_h1T[Tt][TCH*CHF];     // h1 history, transposed chunked (~138 MB)
__device__ float g_xT[Tt*Bsz];           // x transposed [t][b]
__device__ float g_Wt0[32*32*WTF];       // Whh0 tiled   [nt32][c32][32n][36k]
__device__ float g_Wt1[32*64*WTF];       // [Wih1;Whh1]  [nt32][c64][32n][36k]
__device__ float g_WtF[32*32*WFCF];      // Wfc tiled    [vt32][c32][128n][36k]

// ---- ptx helpers ----
__device__ __forceinline__ uint32_t s2u(const void* p){
  return (uint32_t)__cvta_generic_to_shared(p);
}
__device__ __forceinline__ void mbar_init(uint32_t mb){
  asm volatile("mbarrier.init.shared::cta.b64 [%0], 1;" :: "r"(mb));
}
__device__ __forceinline__ void mbar_expect(uint32_t mb, uint32_t tx){
  asm volatile("mbarrier.arrive.expect_tx.shared::cta.b64 _, [%0], %1;" :: "r"(mb), "r"(tx) : "memory");
}
__device__ __forceinline__ void bulk_ld(uint32_t dst, const void* src, uint32_t bytes, uint32_t mb){
  asm volatile("cp.async.bulk.shared::cta.global.mbarrier::complete_tx::bytes [%0], [%1], %2, [%3];"
               :: "r"(dst), "l"(src), "r"(bytes), "r"(mb) : "memory");
}
__device__ __forceinline__ void mbar_wait(uint32_t mb, uint32_t ph){
  uint32_t done = 0;
  do {
    asm volatile("{\n\t.reg .pred p;\n\t"
                 "mbarrier.try_wait.parity.shared::cta.b64 p, [%1], %2;\n\t"
                 "selp.b32 %0,1,0,p;\n\t}"
                 : "=r"(done) : "r"(mb), "r"(ph) : "memory");
  } while(!done);
}

// ---------------------------------------------------------------------------
// Prologue: re-tile weights + transpose x into bulk-copy-friendly layouts.
// ---------------------------------------------------------------------------
#define N_WT0 (32*32*WTF)
#define N_WT1 (32*64*WTF)
#define N_WTF (32*32*WFCF)
#define N_XT  (Tt*Bsz)
#define N_TOT (N_WT0+N_WT1+N_WTF+N_XT)

__global__ void pretile(const float* __restrict__ x,
                        const float* __restrict__ Whh0,
                        const float* __restrict__ Wih1,
                        const float* __restrict__ Whh1,
                        const float* __restrict__ Wfc)
{
  for (long long i = (long long)blockIdx.x*blockDim.x + threadIdx.x; i < N_TOT;
       i += (long long)gridDim.x*blockDim.x){
    long long j = i;
    if (j < N_WT0){
      int nt = (int)(j/(32*WTF)); int r = (int)(j%(32*WTF));
      int c = r/WTF; int q = r%WTF; int nl = q/36, kk = q%36;
      int n = nt*32+nl;
      g_Wt0[j] = (kk<32) ? Whh0[n*Hh + c*32 + kk] : 0.f;
      continue;
    }
    j -= N_WT0;
    if (j < N_WT1){
      int nt = (int)(j/(64*WTF)); int r = (int)(j%(64*WTF));
      int c = r/WTF; int q = r%WTF; int nl = q/36, kk = q%36;
      int n = nt*32+nl;
      float v = 0.f;
      if (kk<32) v = (c<32) ? Wih1[n*Hh + c*32 + kk] : Whh1[n*Hh + (c-32)*32 + kk];
      g_Wt1[(long long)(nt*64 + c)*WTF + q] = v;
      continue;
    }
    j -= N_WT1;
    if (j < N_WTF){
      int vt = (int)(j/(32*WFCF)); int r = (int)(j%(32*WFCF));
      int c = r/WFCF; int q = r%WFCF; int nl = q/36, kk = q%36;
      int n = vt*128+nl;
      g_WtF[(long long)(vt*32 + c)*WFCF + q] = (kk<32) ? Wfc[(size_t)n*Hh + c*32 + kk] : 0.f;
      continue;
    }
    j -= N_WTF;
    { int t = (int)(j/Bsz), b = (int)(j%Bsz); g_xT[t*Bsz + b] = x[(size_t)b*Tt + t]; }
  }
}

// ---------------------------------------------------------------------------
// Recurrence step (pipelined across launches). Launch k in 0..T:
//  blocks 0..31  (k<T):  h0[k]   = tanh(x_k*Wih0 + h0[k-1]@Whh0^T + b0)
//  blocks 32..63 (k>=1): h1[k-1] = tanh(h0[k-1]@Wih1^T + h1[k-2]@Whh1^T + b1)
// h1-history writes use __stcs (evict-first) so the 131 MB stream does not
// evict the per-step weight tiles from L2.
// ---------------------------------------------------------------------------
#define RS_STGF 5376            // stage floats: 4224 A + 1152 B
#define RS_SMEM (4*RS_STGF*4)   // 86016 B

__global__ void __launch_bounds__(256) rnn_step(
  const float* __restrict__ Wih0,
  const float* __restrict__ bih0, const float* __restrict__ bhh0,
  const float* __restrict__ bih1, const float* __restrict__ bhh1,
  int k)
{
  extern __shared__ __align__(16) float sm[];
  __shared__ __align__(8) uint64_t mbar_s[4];
  const int tid = threadIdx.x, w = tid>>5;
  const bool is1 = (blockIdx.x >= 32);
  if (!is1 && k==Tt) return;
  if ( is1 && k==0 ) return;
  const int nt = is1 ? (int)blockIdx.x-32 : (int)blockIdx.x;
  const int n0 = nt*32;

  const float* h0prev  = g_h0T[(k+1)&1];
  const float* h1prev2 = (k>=2) ? g_h1T[k-2] : g_h1T[0];
  const int nc = is1 ? ((k>=2)?64:32) : ((k>=1)?32:0);

  wmma::fragment<wmma::accumulator,16,16,8,float> c0,c1;
  wmma::fill_fragment(c0,0.f); wmma::fill_fragment(c1,0.f);

  if (nc > 0){
    const uint32_t smb = s2u(sm);
    const uint32_t mbb = s2u(mbar_s);
    if (tid==0){
      #pragma unroll
      for (int s=0;s<4;s++) mbar_init(mbb+8*s);
      asm volatile("fence.proxy.async.shared::cta;" ::: "memory");
    }
    __syncthreads();

    auto issue = [&](int c){
      const int s = c&3;
      const uint32_t mb = mbb + 8*s;
      mbar_expect(mb, CHB + 4608);
      const float* asrc; const float* bsrc;
      if (!is1){ asrc = h0prev + c*CHF;  bsrc = g_Wt0 + (nt*32 + c)*WTF; }
      else     { asrc = (c<32) ? h0prev + c*CHF : h1prev2 + (c-32)*CHF;
                 bsrc = g_Wt1 + (nt*64 + c)*WTF; }
      const uint32_t da = smb + (uint32_t)s*RS_STGF*4;
      bulk_ld(da,        asrc, CHB,  mb);
      bulk_ld(da+CHB,    bsrc, 4608, mb);
    };
    if (tid==0){ const int pre = nc<4?nc:4; for (int c=0;c<pre;c++) issue(c); }

    for (int c=0;c<nc;c++){
      mbar_wait(mbb + 8*(c&3), (uint32_t)((c>>2)&1));
      const float* a_s = sm + (c&3)*RS_STGF;
      const float* b_s = a_s + CHF;
      #pragma unroll
      for (int kk=0;kk<4;kk++){
        wmma::fragment<wmma::matrix_a,16,16,8,wmma::precision::tf32,wmma::col_major> af;
        wmma::load_matrix_sync(af, a_s + kk*8*132 + w*16, 132);
        #pragma unroll
        for (int e=0;e<af.num_elements;e++) af.x[e]=wmma::__float_to_tf32(af.x[e]);
        wmma::fragment<wmma::matrix_b,16,16,8,wmma::precision::tf32,wmma::col_major> bf;
        wmma::load_matrix_sync(bf, b_s + kk*8, 36);
        #pragma unroll
        for (int e=0;e<bf.num_elements;e++) bf.x[e]=wmma::__float_to_tf32(bf.x[e]);
        wmma::mma_sync(c0, af, bf, c0);
        wmma::load_matrix_sync(bf, b_s + 16*36 + kk*8, 36);
        #pragma unroll
        for (int e=0;e<bf.num_elements;e++) bf.x[e]=wmma::__float_to_tf32(bf.x[e]);
        wmma::mma_sync(c1, af, bf, c1);
      }
      __syncthreads();
      if (tid==0 && c+4<nc) issue(c+4);
    }
  }

  // epilogue: stage 128x32 tile [128][36], bias(+input), tanh, write transposed
  float* stg = sm;
  wmma::store_matrix_sync(stg + (w*16)*36,      c0, 36, wmma::mem_row_major);
  wmma::store_matrix_sync(stg + (w*16)*36 + 16, c1, 36, wmma::mem_row_major);
  __syncthreads();

  if (!is1){
    float* dst = g_h0T[k&1];
    #pragma unroll
    for (int i=0;i<16;i++){
      int f = tid + i*256;
      int nl = f>>7, b = f&127, n = n0+nl;
      float v = stg[b*36+nl] + g_xT[k*Bsz+b]*Wih0[n] + bih0[n] + bhh0[n];
      dst[(n>>5)*CHF + (n&31)*132 + b] = tanhf(v);     // re-read next step: normal caching
    }
  } else {
    float* dst = g_h1T[k-1];
    #pragma unroll
    for (int i=0;i<16;i++){
      int f = tid + i*256;
      int nl = f>>7, b = f&127, n = n0+nl;
      float v = stg[b*36+nl] + bih1[n] + bhh1[n];
      __stcs(&dst[(n>>5)*CHF + (n&31)*132 + b], tanhf(v));   // streaming: protect L2 weights
    }
  }
}

// ---------------------------------------------------------------------------
// FC: out[b,t,v] = h1[t][b,:] @ Wfc[v,:] + bfc[v]
// CTA tile: BM=256 (two timesteps) x BN=128, 3-stage bulk pipeline.
// Output stores are evict-first (__stcs) to protect A/W reuse in L2.
// ---------------------------------------------------------------------------
#define FC_STGF 13056          // 2*4224 A + 4608 B floats
#define FC_SMEM (3*FC_STGF*4)  // 156672 B

__global__ void __launch_bounds__(256) fc2(const float* __restrict__ bfc,
                                           float* __restrict__ out)
{
  extern __shared__ __align__(16) float sm[];
  __shared__ __align__(8) uint64_t mbar_s[3];
  const int tid = threadIdx.x, w = tid>>5, wm = w&3, wn = w>>2;
  const int vt = blockIdx.x, mt = blockIdx.y;
  const float* A0 = g_h1T[2*mt];
  const float* A1 = g_h1T[2*mt+1];

  wmma::fragment<wmma::accumulator,16,16,8,float> cf[4][4];
  #pragma unroll
  for (int i=0;i<4;i++)
    #pragma unroll
    for (int j=0;j<4;j++) wmma::fill_fragment(cf[i][j],0.f);

  const uint32_t smb = s2u(sm);
  const uint32_t mbb = s2u(mbar_s);
  if (tid==0){
    #pragma unroll
    for (int s=0;s<3;s++) mbar_init(mbb+8*s);
    asm volatile("fence.proxy.async.shared::cta;" ::: "memory");
  }
  __syncthreads();

  auto issue = [&](int c){
    const int s = c%3;
    const uint32_t mb = mbb + 8*s;
    mbar_expect(mb, 2*CHB + 18432);
    const uint32_t da = smb + (uint32_t)s*FC_STGF*4;
    bulk_ld(da,         A0 + c*CHF, CHB, mb);
    bulk_ld(da+CHB,     A1 + c*CHF, CHB, mb);
    bulk_ld(da+2*CHB,   g_WtF + (size_t)(vt*32 + c)*WFCF, 18432, mb);
  };
  if (tid==0){ for (int c=0;c<3;c++) issue(c); }

  for (int c=0;c<32;c++){
    mbar_wait(mbb + 8*(c%3), (uint32_t)((c/3)&1));
    const float* st = sm + (c%3)*FC_STGF;
    const float* b_s = st + 2*CHF;
    #pragma unroll
    for (int kk=0;kk<4;kk++){
      wmma::fragment<wmma::matrix_a,16,16,8,wmma::precision::tf32,wmma::col_major> af[4];
      #pragma unroll
      for (int i=0;i<4;i++){
        int m = wm*64 + i*16;
        const float* ab = (m>=128) ? (st+CHF) : st;
        wmma::load_matrix_sync(af[i], ab + kk*8*132 + (m&127), 132);
        #pragma unroll
        for (int e=0;e<af[i].num_elements;e++) af[i].x[e]=wmma::__float_to_tf32(af[i].x[e]);
      }
      #pragma unroll
      for (int j=0;j<4;j++){
        wmma::fragment<wmma::matrix_b,16,16,8,wmma::precision::tf32,wmma::col_major> bf;
        wmma::load_matrix_sync(bf, b_s + (wn*64 + j*16)*36 + kk*8, 36);
        #pragma unroll
        for (int e=0;e<bf.num_elements;e++) bf.x[e]=wmma::__float_to_tf32(bf.x[e]);
        #pragma unroll
        for (int i=0;i<4;i++) wmma::mma_sync(cf[i][j], af[i], bf, cf[i][j]);
      }
    }
    __syncthreads();
    if (tid==0 && c+3<32) issue(c+3);
  }

  // epilogue: two 256x64 halves via smem [256][68], bias, streaming float4 stores
  float* stg = sm;
  #pragma unroll
  for (int h=0; h<2; h++){
    if (wn==h){
      #pragma unroll
      for (int i=0;i<4;i++)
        #pragma unroll
        for (int j=0;j<4;j++)
          wmma::store_matrix_sync(stg + (wm*64+i*16)*68 + j*16, cf[i][j], 68, wmma::mem_row_major);
    }
    __syncthreads();
    #pragma unroll
    for (int i=0;i<16;i++){
      int f = tid + i*256;
      int r = f>>4, c4 = f&15;
      int n = vt*128 + h*64 + c4*4;
      float4 v  = *(float4*)(stg + r*68 + c4*4);
      float4 bb = *(const float4*)(bfc + n);
      v.x+=bb.x; v.y+=bb.y; v.z+=bb.z; v.w+=bb.w;
      int b = r&127, t = 2*mt + (r>>7);
      __stcs((float4*)(out + ((size_t)b*Tt + t)*(size_t)Vv + n), v);
    }
    __syncthreads();
  }
}

// Final hidden states -> out tail [2, B, H] (de-transpose from chunked layout)
__global__ void states_kernel(float* __restrict__ out){
  int i = blockIdx.x*blockDim.x + threadIdx.x;
  if (i >= 2*BH) return;
  const size_t BTV = (size_t)Bsz*Tt*Vv;
  int layer = i >= BH;
  int j = i - layer*BH;
  int b = j>>10, n = j&1023;
  const float* src = layer ? g_h1T[Tt-1] : g_h0T[(Tt-1)&1];
  out[BTV + i] = src[(n>>5)*CHF + (n&31)*132 + b];
}

extern "C" void kernel_launch(void* const* d_in, const int* in_sizes, int n_in,
                              void* d_out, int out_size) {
  const float* x    = (const float*)d_in[0];
  const float* Wih0 = (const float*)d_in[1];
  const float* Whh0 = (const float*)d_in[2];
  const float* bih0 = (const float*)d_in[3];
  const float* bhh0 = (const float*)d_in[4];
  const float* Wih1 = (const float*)d_in[5];
  const float* Whh1 = (const float*)d_in[6];
  const float* bih1 = (const float*)d_in[7];
  const float* bhh1 = (const float*)d_in[8];
  const float* Wfc  = (const float*)d_in[9];
  const float* bfc  = (const float*)d_in[10];
  float* out = (float*)d_out;

  cudaFuncSetAttribute(rnn_step, cudaFuncAttributeMaxDynamicSharedMemorySize, RS_SMEM);
  cudaFuncSetAttribute(fc2,      cudaFuncAttributeMaxDynamicSharedMemorySize, FC_SMEM);

  // 1) re-tile weights + x into bulk-friendly layouts
  pretile<<<4096, 256>>>(x, Whh0, Wih1, Whh1, Wfc);

  // 2) pipelined recurrence: launch k computes h0[k] and h1[k-1]
  for (int k = 0; k <= Tt; ++k)
    rnn_step<<<64, 256, RS_SMEM>>>(Wih0, bih0, bhh0, bih1, bhh1, k);

  // 3) batched trailing linear
  fc2<<<dim3(32,128), 256, FC_SMEM>>>(bfc, out);

  // 4) final states tail
  long long need = (long long)Bsz*Tt*Vv + 2LL*BH;
  if ((long long)out_size >= need)
    states_kernel<<<(2*BH + 255)/256, 256>>>(out);
}

// round 8
// speedup vs baseline: 1.1601x; 1.1576x over previous
#include <cuda_runtime.h>
#include <mma.h>
#include <cstdint>

using namespace nvcuda;

#define Bsz 128
#define Tt  256
#define Hh  1024
#define Vv  4096
#define BH  (Bsz*Hh)

#define CHF  4224          // floats per A-chunk: 32 k-rows * 132 (128 b + 4 pad)
#define CHB  16896         // bytes per A-chunk
#define TCH  32            // chunks per K=1024
#define WTF  1152          // floats per 32n x 36k weight tile chunk (4608 B)
#define WFCF 4608          // floats per 128n x 36k FC weight tile chunk (18432 B)
#define WSLF 36864         // floats per CTA weight slab (147456 B) for both L0/L1
#define NCTA 96

// ---- device scratch (static globals; no allocation) ----
__device__ float g_h0T[2][TCH*CHF];      // h0 state, transposed chunked, double buffer
__device__ float g_h1T[Tt][TCH*CHF];     // h1 history, transposed chunked (~138 MB)
__device__ float g_xT[Tt*Bsz];           // x transposed [t][b]
__device__ float g_Wt0[32*WSLF];         // Whh0 tiled   [nt32][c32][32n][36k] (tf32-rounded)
__device__ float g_Wt1[64*WSLF];         // [Wih1;Whh1]  [nt64(16n)][c64][16n][36k] (tf32-rounded)
__device__ float g_WtF[32*32*WFCF];      // Wfc tiled    [vt32][c32][128n][36k]
__device__ unsigned int g_bar;           // persistent grid barrier counter
__device__ unsigned int g_done;          // end-of-run reset counter

// ---- ptx helpers ----
__device__ __forceinline__ uint32_t s2u(const void* p){
  return (uint32_t)__cvta_generic_to_shared(p);
}
__device__ __forceinline__ void mbar_init(uint32_t mb){
  asm volatile("mbarrier.init.shared::cta.b64 [%0], 1;" :: "r"(mb));
}
__device__ __forceinline__ void mbar_expect(uint32_t mb, uint32_t tx){
  asm volatile("mbarrier.arrive.expect_tx.shared::cta.b64 _, [%0], %1;" :: "r"(mb), "r"(tx) : "memory");
}
__device__ __forceinline__ void bulk_ld(uint32_t dst, const void* src, uint32_t bytes, uint32_t mb){
  asm volatile("cp.async.bulk.shared::cta.global.mbarrier::complete_tx::bytes [%0], [%1], %2, [%3];"
               :: "r"(dst), "l"(src), "r"(bytes), "r"(mb) : "memory");
}
__device__ __forceinline__ void mbar_wait(uint32_t mb, uint32_t ph){
  uint32_t done = 0;
  do {
    asm volatile("{\n\t.reg .pred p;\n\t"
                 "mbarrier.try_wait.parity.shared::cta.b64 p, [%1], %2;\n\t"
                 "selp.b32 %0,1,0,p;\n\t}"
                 : "=r"(done) : "r"(mb), "r"(ph) : "memory");
  } while(!done);
}
__device__ __forceinline__ float rtf32(float x){
  float r; asm("cvt.rna.tf32.f32 %0, %1;" : "=f"(r) : "f"(x)); return r;
}

// ---------------------------------------------------------------------------
// Prologue: re-tile weights (tf32-rounded for the recurrence) + transpose x.
// ---------------------------------------------------------------------------
#define N_WT0 (32*WSLF)
#define N_WT1 (64*WSLF)
#define N_WTF (32*32*WFCF)
#define N_XT  (Tt*Bsz)
#define N_TOT (N_WT0+N_WT1+N_WTF+N_XT)

__global__ void pretile(const float* __restrict__ x,
                        const float* __restrict__ Whh0,
                        const float* __restrict__ Wih1,
                        const float* __restrict__ Whh1,
                        const float* __restrict__ Wfc)
{
  for (long long i = (long long)blockIdx.x*blockDim.x + threadIdx.x; i < N_TOT;
       i += (long long)gridDim.x*blockDim.x){
    long long j = i;
    if (j < N_WT0){
      // L0 slab: [nt32][c32][32n][36k]
      int nt = (int)(j/WSLF); int r = (int)(j%WSLF);
      int c = r/WTF; int q = r%WTF; int nl = q/36, kk = q%36;
      int n = nt*32+nl;
      g_Wt0[j] = (kk<32) ? rtf32(Whh0[n*Hh + c*32 + kk]) : 0.f;
      continue;
    }
    j -= N_WT0;
    if (j < N_WT1){
      // L1 slab: [nt64 of 16n][c64][16n][36k]; c<32: Wih1, c>=32: Whh1
      int nt = (int)(j/WSLF); int r = (int)(j%WSLF);
      int c = r/576; int q = r%576; int nl = q/36, kk = q%36;
      int n = nt*16+nl;
      float v = 0.f;
      if (kk<32) v = (c<32) ? Wih1[n*Hh + c*32 + kk] : Whh1[n*Hh + (c-32)*32 + kk];
      g_Wt1[(long long)nt*WSLF + r] = rtf32(v);
      continue;
    }
    j -= N_WT1;
    if (j < N_WTF){
      int vt = (int)(j/(32*WFCF)); int r = (int)(j%(32*WFCF));
      int c = r/WFCF; int q = r%WFCF; int nl = q/36, kk = q%36;
      int n = vt*128+nl;
      g_WtF[(long long)(vt*32 + c)*WFCF + q] = (kk<32) ? Wfc[(size_t)n*Hh + c*32 + kk] : 0.f;
      continue;
    }
    j -= N_WTF;
    { int t = (int)(j/Bsz), b = (int)(j%Bsz); g_xT[t*Bsz + b] = x[(size_t)b*Tt + t]; }
  }
}

// ---------------------------------------------------------------------------
// Persistent recurrence: one kernel, 96 CTAs, weights resident in SMEM.
//  CTAs 0..31  (L0, 32n each): h0[t]   = tanh(x_t*Wih0 + h0[t-1]@Whh0^T + b0)
//  CTAs 32..95 (L1, 16n each): h1[t-1] = tanh(h0[t-1]@Wih1^T + h1[t-2]@Whh1^T + b1)
// Grid-wide atomic barrier between steps; monotonic counter, reset at end.
// SMEM: 36864 floats weights + 3*4224 floats A-staging = 198144 B.
// ---------------------------------------------------------------------------
#define RP_SMEM ((WSLF + 3*CHF)*4)

__global__ void __launch_bounds__(256) rnn_persist(
  const float* __restrict__ Wih0,
  const float* __restrict__ bih0, const float* __restrict__ bhh0,
  const float* __restrict__ bih1, const float* __restrict__ bhh1)
{
  extern __shared__ __align__(16) float sm[];
  __shared__ __align__(8) uint64_t mbs[4];
  __shared__ float biasb[64];
  const int tid = threadIdx.x, w = tid>>5;
  const bool is1 = (blockIdx.x >= 32);
  const int nt = is1 ? (int)blockIdx.x - 32 : (int)blockIdx.x;
  const int n0 = is1 ? nt*16 : nt*32;

  float* ws   = sm;            // weight slab: 36864 floats
  float* astg = sm + WSLF;     // 3 A stages x 4224 floats

  const uint32_t asb = s2u(astg);
  const uint32_t mbb = s2u(mbs);

  if (tid==0){
    #pragma unroll
    for (int s=0;s<4;s++) mbar_init(mbb+8*s);
    asm volatile("fence.proxy.async.shared::cta;" ::: "memory");
  }
  __syncthreads();

  // One-time weight residency load (9 x 16 KB bulks)
  if (tid==0){
    const float* wsrc = is1 ? (g_Wt1 + (size_t)nt*WSLF) : (g_Wt0 + (size_t)nt*WSLF);
    mbar_expect(mbb+24, (uint32_t)(WSLF*4));
    #pragma unroll
    for (int i=0;i<9;i++) bulk_ld(s2u(ws) + i*16384u, wsrc + i*4096, 16384u, mbb+24);
  }
  if (!is1){
    if (tid<32){ int n=n0+tid; biasb[tid]=bih0[n]+bhh0[n]; biasb[32+tid]=Wih0[n]; }
  } else {
    if (tid<16){ int n=n0+tid; biasb[tid]=bih1[n]+bhh1[n]; }
  }
  mbar_wait(mbb+24, 0u);
  __syncthreads();

  unsigned phv0=0, phv1=0, phv2=0;

  for (int t=0; t<=Tt; ++t){
    const bool active = (!is1 && t<Tt) || (is1 && t>=1);
    if (active){
      const float* h0prev  = g_h0T[(t+1)&1];
      const float* h1prev2 = (t>=2) ? g_h1T[t-2] : g_h1T[0];
      const int nc = is1 ? ((t>=2)?64:32) : ((t>=1)?32:0);

      wmma::fragment<wmma::accumulator,16,16,8,float> c0,c1;
      wmma::fill_fragment(c0,0.f); wmma::fill_fragment(c1,0.f);

      if (nc > 0){
        auto srcp = [&](int c)->const float*{
          if (!is1) return h0prev + c*CHF;
          return (c<32) ? h0prev + c*CHF : h1prev2 + (c-32)*CHF;
        };
        if (tid==0){
          for (int c=0;c<3;c++){
            mbar_expect(mbb+8u*(c%3), CHB);
            bulk_ld(asb + (uint32_t)(c%3)*CHB, srcp(c), CHB, mbb+8u*(c%3));
          }
        }
        for (int c=0;c<nc;c++){
          const int s = c%3;
          unsigned ph = (s==0)?phv0:((s==1)?phv1:phv2);
          mbar_wait(mbb+8u*s, ph);
          if (s==0) phv0^=1; else if (s==1) phv1^=1; else phv2^=1;
          const float* a_s = astg + s*CHF;
          const float* b_s = ws + (is1 ? c*576 : c*1152);
          #pragma unroll
          for (int kk=0;kk<4;kk++){
            wmma::fragment<wmma::matrix_a,16,16,8,wmma::precision::tf32,wmma::col_major> af;
            wmma::load_matrix_sync(af, a_s + kk*8*132 + w*16, 132);
            #pragma unroll
            for (int e=0;e<af.num_elements;e++) af.x[e]=wmma::__float_to_tf32(af.x[e]);
            wmma::fragment<wmma::matrix_b,16,16,8,wmma::precision::tf32,wmma::col_major> bf;
            wmma::load_matrix_sync(bf, b_s + kk*8, 36);        // pre-rounded tf32
            wmma::mma_sync(c0, af, bf, c0);
            if (!is1){
              wmma::fragment<wmma::matrix_b,16,16,8,wmma::precision::tf32,wmma::col_major> bf2;
              wmma::load_matrix_sync(bf2, b_s + 16*36 + kk*8, 36);
              wmma::mma_sync(c1, af, bf2, c1);
            }
          }
          __syncthreads();
          if (tid==0 && c+3<nc){
            mbar_expect(mbb+8u*s, CHB);
            bulk_ld(asb + (uint32_t)s*CHB, srcp(c+3), CHB, mbb+8u*s);
          }
        }
      }

      // epilogue via smem staging (reuses A staging region; protected by syncs)
      float* stg = astg;
      wmma::store_matrix_sync(stg + (w*16)*36, c0, 36, wmma::mem_row_major);
      if (!is1) wmma::store_matrix_sync(stg + (w*16)*36 + 16, c1, 36, wmma::mem_row_major);
      __syncthreads();

      if (!is1){
        float* dst = g_h0T[t&1];
        #pragma unroll
        for (int i=0;i<16;i++){
          int f = tid + i*256;
          int nl = f>>7, b = f&127, n = n0+nl;
          float v = stg[b*36+nl] + g_xT[t*Bsz+b]*biasb[32+nl] + biasb[nl];
          dst[(n>>5)*CHF + (n&31)*132 + b] = tanhf(v);
        }
      } else {
        float* dst = g_h1T[t-1];
        #pragma unroll
        for (int i=0;i<8;i++){
          int f = tid + i*256;
          int nl = f>>7, b = f&127, n = n0+nl;
          float v = stg[b*36+nl] + biasb[nl];
          __stcs(&dst[(n>>5)*CHF + (n&31)*132 + b], tanhf(v));
        }
      }
    }

    // grid-wide barrier between steps (not after the last)
    if (t < Tt){
      __threadfence();
      __syncthreads();
      if (tid==0){
        atomicAdd(&g_bar, 1u);
        const unsigned target = (unsigned)NCTA * (unsigned)(t+1);
        while (*((volatile unsigned int*)&g_bar) < target) { }
      }
      __syncthreads();
      __threadfence();
    }
  }

  // end-of-run counter reset (last CTA of 96; others never touch counters again)
  __syncthreads();
  if (tid==0){
    __threadfence();
    unsigned d = atomicAdd(&g_done, 1u);
    if (d == (unsigned)(NCTA-1)){
      g_bar = 0u;
      __threadfence();
      g_done = 0u;
    }
  }
}

// ---------------------------------------------------------------------------
// FC: out[b,t,v] = h1[t][b,:] @ Wfc[v,:] + bfc[v]  (unchanged from R7)
// ---------------------------------------------------------------------------
#define FC_STGF 13056          // 2*4224 A + 4608 B floats
#define FC_SMEM (3*FC_STGF*4)  // 156672 B

__global__ void __launch_bounds__(256) fc2(const float* __restrict__ bfc,
                                           float* __restrict__ out)
{
  extern __shared__ __align__(16) float sm[];
  __shared__ __align__(8) uint64_t mbar_s[3];
  const int tid = threadIdx.x, w = tid>>5, wm = w&3, wn = w>>2;
  const int vt = blockIdx.x, mt = blockIdx.y;
  const float* A0 = g_h1T[2*mt];
  const float* A1 = g_h1T[2*mt+1];

  wmma::fragment<wmma::accumulator,16,16,8,float> cf[4][4];
  #pragma unroll
  for (int i=0;i<4;i++)
    #pragma unroll
    for (int j=0;j<4;j++) wmma::fill_fragment(cf[i][j],0.f);

  const uint32_t smb = s2u(sm);
  const uint32_t mbb = s2u(mbar_s);
  if (tid==0){
    #pragma unroll
    for (int s=0;s<3;s++) mbar_init(mbb+8*s);
    asm volatile("fence.proxy.async.shared::cta;" ::: "memory");
  }
  __syncthreads();

  auto issue = [&](int c){
    const int s = c%3;
    const uint32_t mb = mbb + 8*s;
    mbar_expect(mb, 2*CHB + 18432);
    const uint32_t da = smb + (uint32_t)s*FC_STGF*4;
    bulk_ld(da,         A0 + c*CHF, CHB, mb);
    bulk_ld(da+CHB,     A1 + c*CHF, CHB, mb);
    bulk_ld(da+2*CHB,   g_WtF + (size_t)(vt*32 + c)*WFCF, 18432, mb);
  };
  if (tid==0){ for (int c=0;c<3;c++) issue(c); }

  for (int c=0;c<32;c++){
    mbar_wait(mbb + 8*(c%3), (uint32_t)((c/3)&1));
    const float* st = sm + (c%3)*FC_STGF;
    const float* b_s = st + 2*CHF;
    #pragma unroll
    for (int kk=0;kk<4;kk++){
      wmma::fragment<wmma::matrix_a,16,16,8,wmma::precision::tf32,wmma::col_major> af[4];
      #pragma unroll
      for (int i=0;i<4;i++){
        int m = wm*64 + i*16;
        const float* ab = (m>=128) ? (st+CHF) : st;
        wmma::load_matrix_sync(af[i], ab + kk*8*132 + (m&127), 132);
        #pragma unroll
        for (int e=0;e<af[i].num_elements;e++) af[i].x[e]=wmma::__float_to_tf32(af[i].x[e]);
      }
      #pragma unroll
      for (int j=0;j<4;j++){
        wmma::fragment<wmma::matrix_b,16,16,8,wmma::precision::tf32,wmma::col_major> bf;
        wmma::load_matrix_sync(bf, b_s + (wn*64 + j*16)*36 + kk*8, 36);
        #pragma unroll
        for (int e=0;e<bf.num_elements;e++) bf.x[e]=wmma::__float_to_tf32(bf.x[e]);
        #pragma unroll
        for (int i=0;i<4;i++) wmma::mma_sync(cf[i][j], af[i], bf, cf[i][j]);
      }
    }
    __syncthreads();
    if (tid==0 && c+3<32) issue(c+3);
  }

  float* stg = sm;
  #pragma unroll
  for (int h=0; h<2; h++){
    if (wn==h){
      #pragma unroll
      for (int i=0;i<4;i++)
        #pragma unroll
        for (int j=0;j<4;j++)
          wmma::store_matrix_sync(stg + (wm*64+i*16)*68 + j*16, cf[i][j], 68, wmma::mem_row_major);
    }
    __syncthreads();
    #pragma unroll
    for (int i=0;i<16;i++){
      int f = tid + i*256;
      int r = f>>4, c4 = f&15;
      int n = vt*128 + h*64 + c4*4;
      float4 v  = *(float4*)(stg + r*68 + c4*4);
      float4 bb = *(const float4*)(bfc + n);
      v.x+=bb.x; v.y+=bb.y; v.z+=bb.z; v.w+=bb.w;
      int b = r&127, t = 2*mt + (r>>7);
      __stcs((float4*)(out + ((size_t)b*Tt + t)*(size_t)Vv + n), v);
    }
    __syncthreads();
  }
}

// Final hidden states -> out tail [2, B, H] (de-transpose from chunked layout)
__global__ void states_kernel(float* __restrict__ out){
  int i = blockIdx.x*blockDim.x + threadIdx.x;
  if (i >= 2*BH) return;
  const size_t BTV = (size_t)Bsz*Tt*Vv;
  int layer = i >= BH;
  int j = i - layer*BH;
  int b = j>>10, n = j&1023;
  const float* src = layer ? g_h1T[Tt-1] : g_h0T[(Tt-1)&1];
  out[BTV + i] = src[(n>>5)*CHF + (n&31)*132 + b];
}

extern "C" void kernel_launch(void* const* d_in, const int* in_sizes, int n_in,
                              void* d_out, int out_size) {
  const float* x    = (const float*)d_in[0];
  const float* Wih0 = (const float*)d_in[1];
  const float* Whh0 = (const float*)d_in[2];
  const float* bih0 = (const float*)d_in[3];
  const float* bhh0 = (const float*)d_in[4];
  const float* Wih1 = (const float*)d_in[5];
  const float* Whh1 = (const float*)d_in[6];
  const float* bih1 = (const float*)d_in[7];
  const float* bhh1 = (const float*)d_in[8];
  const float* Wfc  = (const float*)d_in[9];
  const float* bfc  = (const float*)d_in[10];
  float* out = (float*)d_out;

  cudaFuncSetAttribute(rnn_persist, cudaFuncAttributeMaxDynamicSharedMemorySize, RP_SMEM);
  cudaFuncSetAttribute(fc2,         cudaFuncAttributeMaxDynamicSharedMemorySize, FC_SMEM);

  // 1) re-tile weights (tf32-rounded for recurrence) + transpose x
  pretile<<<4096, 256>>>(x, Whh0, Wih1, Whh1, Wfc);

  // 2) persistent recurrence: all 257 steps in ONE kernel, weights SMEM-resident
  rnn_persist<<<NCTA, 256, RP_SMEM>>>(Wih0, bih0, bhh0, bih1, bhh1);

  // 3) batched trailing linear
  fc2<<<dim3(32,128), 256, FC_SMEM>>>(bfc, out);

  // 4) final states tail
  long long need = (long long)Bsz*Tt*Vv + 2LL*BH;
  if ((long long)out_size >= need)
    states_kernel<<<(2*BH + 255)/256, 256>>>(out);
}

// round 10
// speedup vs baseline: 1.2744x; 1.0985x over previous
#include <cuda_runtime.h>
#include <mma.h>
#include <cstdint>

using namespace nvcuda;

#define Bsz 128
#define Tt  256
#define Hh  1024
#define Vv  4096
#define BH  (Bsz*Hh)

#define CHF  4224          // floats per A-chunk: 32 k-rows * 132 (128 b + 4 pad)
#define CHB  16896         // bytes per A-chunk
#define TCH  32            // chunks per K=1024
#define WTF  1152          // floats per 32n x 36k weight tile chunk (4608 B)
#define WFCF 4608          // floats per 128n x 36k FC weight tile chunk (18432 B)
#define WSLF 36864         // floats per CTA weight slab (147456 B) for both L0/L1
#define NCTA 96

// ---- device scratch (static globals; no allocation) ----
__device__ float g_h0T[2][TCH*CHF];      // h0 state, transposed chunked, double buffer
__device__ float g_h1T[Tt][TCH*CHF];     // h1 history, transposed chunked (~138 MB)
__device__ float g_xT[Tt*Bsz];           // x transposed [t][b]
__device__ float g_Wt0[32*WSLF];         // Whh0 tiled   [nt32][c32][32n][36k] (tf32-rounded)
__device__ float g_Wt1[64*WSLF];         // [Wih1;Whh1]  [nt64(16n)][c64][16n][36k] (tf32-rounded)
__device__ float g_WtF[32*32*WFCF];      // Wfc tiled    [vt32][c32][128n][36k]
__device__ unsigned int g_bar;           // persistent grid barrier counter
__device__ unsigned int g_done;          // end-of-run reset counter

// ---- ptx helpers ----
__device__ __forceinline__ uint32_t s2u(const void* p){
  return (uint32_t)__cvta_generic_to_shared(p);
}
__device__ __forceinline__ void mbar_init(uint32_t mb, uint32_t cnt){
  asm volatile("mbarrier.init.shared::cta.b64 [%0], %1;" :: "r"(mb), "r"(cnt));
}
__device__ __forceinline__ void mbar_expect(uint32_t mb, uint32_t tx){
  asm volatile("mbarrier.arrive.expect_tx.shared::cta.b64 _, [%0], %1;" :: "r"(mb), "r"(tx) : "memory");
}
__device__ __forceinline__ void mbar_arrive(uint32_t mb){
  asm volatile("mbarrier.arrive.shared::cta.b64 _, [%0];" :: "r"(mb) : "memory");
}
__device__ __forceinline__ void bulk_ld(uint32_t dst, const void* src, uint32_t bytes, uint32_t mb){
  asm volatile("cp.async.bulk.shared::cta.global.mbarrier::complete_tx::bytes [%0], [%1], %2, [%3];"
               :: "r"(dst), "l"(src), "r"(bytes), "r"(mb) : "memory");
}
__device__ __forceinline__ void mbar_wait(uint32_t mb, uint32_t ph){
  uint32_t done = 0;
  do {
    asm volatile("{\n\t.reg .pred p;\n\t"
                 "mbarrier.try_wait.parity.shared::cta.b64 p, [%1], %2;\n\t"
                 "selp.b32 %0,1,0,p;\n\t}"
                 : "=r"(done) : "r"(mb), "r"(ph) : "memory");
  } while(!done);
}
__device__ __forceinline__ float rtf32(float x){
  float r; asm("cvt.rna.tf32.f32 %0, %1;" : "=f"(r) : "f"(x)); return r;
}

// ---------------------------------------------------------------------------
// Prologue: re-tile weights (tf32-rounded for the recurrence) + transpose x.
// ---------------------------------------------------------------------------
#define N_WT0 (32*WSLF)
#define N_WT1 (64*WSLF)
#define N_WTF (32*32*WFCF)
#define N_XT  (Tt*Bsz)
#define N_TOT (N_WT0+N_WT1+N_WTF+N_XT)

__global__ void pretile(const float* __restrict__ x,
                        const float* __restrict__ Whh0,
                        const float* __restrict__ Wih1,
                        const float* __restrict__ Whh1,
                        const float* __restrict__ Wfc)
{
  for (long long i = (long long)blockIdx.x*blockDim.x + threadIdx.x; i < N_TOT;
       i += (long long)gridDim.x*blockDim.x){
    long long j = i;
    if (j < N_WT0){
      int nt = (int)(j/WSLF); int r = (int)(j%WSLF);
      int c = r/WTF; int q = r%WTF; int nl = q/36, kk = q%36;
      int n = nt*32+nl;
      g_Wt0[j] = (kk<32) ? rtf32(Whh0[n*Hh + c*32 + kk]) : 0.f;
      continue;
    }
    j -= N_WT0;
    if (j < N_WT1){
      int nt = (int)(j/WSLF); int r = (int)(j%WSLF);
      int c = r/576; int q = r%576; int nl = q/36, kk = q%36;
      int n = nt*16+nl;
      float v = 0.f;
      if (kk<32) v = (c<32) ? Wih1[n*Hh + c*32 + kk] : Whh1[n*Hh + (c-32)*32 + kk];
      g_Wt1[(long long)nt*WSLF + r] = rtf32(v);
      continue;
    }
    j -= N_WT1;
    if (j < N_WTF){
      int vt = (int)(j/(32*WFCF)); int r = (int)(j%(32*WFCF));
      int c = r/WFCF; int q = r%WFCF; int nl = q/36, kk = q%36;
      int n = vt*128+nl;
      g_WtF[(long long)(vt*32 + c)*WFCF + q] = (kk<32) ? Wfc[(size_t)n*Hh + c*32 + kk] : 0.f;
      continue;
    }
    j -= N_WTF;
    { int t = (int)(j/Bsz), b = (int)(j%Bsz); g_xT[t*Bsz + b] = x[(size_t)b*Tt + t]; }
  }
}

// ---------------------------------------------------------------------------
// Persistent recurrence: 96 CTAs x 288 threads (8 consumer warps + 1 producer).
//  CTAs 0..31  (L0, 32n): h0[t]   = tanh(x_t*Wih0 + h0[t-1]@Whh0^T + b0)
//  CTAs 32..95 (L1, 16n): h1[t-1] = tanh(h0[t-1]@Wih1^T + h1[t-2]@Whh1^T + b1)
// Weights SMEM-resident; A-chunks via 4-stage bulk pipe with full/empty mbarriers
// (NO block-wide sync inside the K loop). Grid barrier between steps.
// SMEM: 147456 B weights + 4*16896 B staging = 215040 B.
// ---------------------------------------------------------------------------
#define RP_SMEM ((WSLF + 4*CHF)*4)
#define NTHR 288

__global__ void __launch_bounds__(NTHR) rnn_persist(
  const float* __restrict__ Wih0,
  const float* __restrict__ bih0, const float* __restrict__ bhh0,
  const float* __restrict__ bih1, const float* __restrict__ bhh1)
{
  extern __shared__ __align__(16) float sm[];
  __shared__ __align__(8) uint64_t mbs[9];   // full[0..3], empty[0..3], wbar
  __shared__ float biasb[64];
  const int tid = threadIdx.x, w = tid>>5;
  const bool is1 = (blockIdx.x >= 32);
  const int nt = is1 ? (int)blockIdx.x - 32 : (int)blockIdx.x;
  const int n0 = is1 ? nt*16 : nt*32;

  float* ws   = sm;            // weight slab: 36864 floats
  float* astg = sm + WSLF;     // 4 A stages x 4224 floats

  const uint32_t asb = s2u(astg);
  const uint32_t mbb = s2u(mbs);

  if (tid==0){
    #pragma unroll
    for (int s=0;s<4;s++){ mbar_init(mbb+8*s, 1u); mbar_init(mbb+32+8*s, 8u); }
    mbar_init(mbb+64, 1u);
    asm volatile("fence.proxy.async.shared::cta;" ::: "memory");
  }
  __syncthreads();

  // One-time weight residency load (9 x 16 KB bulks)
  if (tid==0){
    const float* wsrc = is1 ? (g_Wt1 + (size_t)nt*WSLF) : (g_Wt0 + (size_t)nt*WSLF);
    mbar_expect(mbb+64, (uint32_t)(WSLF*4));
    #pragma unroll
    for (int i=0;i<9;i++) bulk_ld(s2u(ws) + i*16384u, wsrc + i*4096, 16384u, mbb+64);
  }
  if (!is1){
    if (tid<32){ int n=n0+tid; biasb[tid]=bih0[n]+bhh0[n]; biasb[32+tid]=Wih0[n]; }
  } else {
    if (tid<16){ int n=n0+tid; biasb[tid]=bih1[n]+bhh1[n]; }
  }
  mbar_wait(mbb+64, 0u);
  __syncthreads();

  // phase state (registers; scalars to avoid local-mem arrays)
  unsigned fp0=0,fp1=0,fp2=0,fp3=0;      // consumer: full-barrier phases
  unsigned pp0=0,pp1=0,pp2=0,pp3=0;      // producer: empty-barrier phases
  int pcount = 0;                        // total chunks issued (producer)

  for (int t=0; t<=Tt; ++t){
    const bool active = (!is1 && t<Tt) || (is1 && t>=1);
    wmma::fragment<wmma::accumulator,16,16,8,float> c0,c1;
    wmma::fill_fragment(c0,0.f); wmma::fill_fragment(c1,0.f);

    if (active){
      const float* h0prev  = g_h0T[(t+1)&1];
      const float* h1prev2 = (t>=2) ? g_h1T[t-2] : g_h1T[0];
      const int nc = is1 ? ((t>=2)?64:32) : 32;

      const int ncr = (!is1 && t==0) ? 0 : nc;    // L0 t==0: input-only step

      if (w < 8){
        // ---- consumers: wait full -> compute -> arrive empty; no block sync ----
        auto consume = [&](int c, int s, unsigned& fp){
          mbar_wait(mbb+8u*s, fp); fp^=1u;
          const float* a_s = astg + s*CHF;
          const float* b_s = ws + (is1 ? c*576 : c*1152);
          #pragma unroll
          for (int kk=0;kk<4;kk++){
            wmma::fragment<wmma::matrix_a,16,16,8,wmma::precision::tf32,wmma::col_major> af;
            wmma::load_matrix_sync(af, a_s + kk*8*132 + w*16, 132);
            #pragma unroll
            for (int e=0;e<af.num_elements;e++) af.x[e]=wmma::__float_to_tf32(af.x[e]);
            wmma::fragment<wmma::matrix_b,16,16,8,wmma::precision::tf32,wmma::col_major> bf;
            wmma::load_matrix_sync(bf, b_s + kk*8, 36);        // pre-rounded tf32
            wmma::mma_sync(c0, af, bf, c0);
            if (!is1){
              wmma::fragment<wmma::matrix_b,16,16,8,wmma::precision::tf32,wmma::col_major> bf2;
              wmma::load_matrix_sync(bf2, b_s + 16*36 + kk*8, 36);
              wmma::mma_sync(c1, af, bf2, c1);
            }
          }
          if ((tid&31)==0) mbar_arrive(mbb+32u+8u*s);
        };
        for (int cb=0; cb<ncr; cb+=4){
          consume(cb+0, 0, fp0);
          consume(cb+1, 1, fp1);
          consume(cb+2, 2, fp2);
          consume(cb+3, 3, fp3);
        }
      } else if (tid == 256){
        // ---- producer: keep 4 stages in flight ----
        auto issue1 = [&](int c, int s, unsigned& pp){
          if (pcount >= 4){ mbar_wait(mbb+32u+8u*s, pp); pp^=1u; }
          mbar_expect(mbb+8u*s, CHB);
          const float* src = (!is1) ? (h0prev + c*CHF)
                             : ((c<32) ? h0prev + c*CHF : h1prev2 + (c-32)*CHF);
          bulk_ld(asb + (uint32_t)s*CHB, src, CHB, mbb+8u*s);
          pcount++;
        };
        for (int cb=0; cb<ncr; cb+=4){
          issue1(cb+0, 0, pp0);
          issue1(cb+1, 1, pp1);
          issue1(cb+2, 2, pp2);
          issue1(cb+3, 3, pp3);
        }
      }

      // all stages consumed; safe to reuse staging region for epilogue
      __syncthreads();
      float* stg = astg;
      if (w < 8){
        wmma::store_matrix_sync(stg + (w*16)*36, c0, 36, wmma::mem_row_major);
        if (!is1) wmma::store_matrix_sync(stg + (w*16)*36 + 16, c1, 36, wmma::mem_row_major);
      }
      __syncthreads();

      if (w < 8){
        if (!is1){
          float* dst = g_h0T[t&1];
          #pragma unroll
          for (int i=0;i<16;i++){
            int f = tid + i*256;
            int nl = f>>7, b = f&127, n = n0+nl;
            float v = stg[b*36+nl] + g_xT[t*Bsz+b]*biasb[32+nl] + biasb[nl];
            dst[(n>>5)*CHF + (n&31)*132 + b] = tanhf(v);
          }
        } else {
          float* dst = g_h1T[t-1];
          #pragma unroll
          for (int i=0;i<8;i++){
            int f = tid + i*256;
            int nl = f>>7, b = f&127, n = n0+nl;
            float v = stg[b*36+nl] + biasb[nl];
            dst[(n>>5)*CHF + (n&31)*132 + b] = tanhf(v);   // plain store: keep in L2
          }
        }
      }
    }

    // grid-wide barrier between steps (not after the last)
    if (t < Tt){
      __threadfence();
      __syncthreads();
      if (tid==0){
        atomicAdd(&g_bar, 1u);
        const unsigned target = (unsigned)NCTA * (unsigned)(t+1);
        while (*((volatile unsigned int*)&g_bar) < target) { }
      }
      __syncthreads();
      __threadfence();
    }
  }

  // end-of-run counter reset (last CTA of 96)
  __syncthreads();
  if (tid==0){
    __threadfence();
    unsigned d = atomicAdd(&g_done, 1u);
    if (d == (unsigned)(NCTA-1)){
      g_bar = 0u;
      __threadfence();
      g_done = 0u;
    }
  }
}

// ---------------------------------------------------------------------------
// FC: out[b,t,v] = h1[t][b,:] @ Wfc[v,:] + bfc[v]  (unchanged)
// ---------------------------------------------------------------------------
#define FC_STGF 13056          // 2*4224 A + 4608 B floats
#define FC_SMEM (3*FC_STGF*4)  // 156672 B

__global__ void __launch_bounds__(256) fc2(const float* __restrict__ bfc,
                                           float* __restrict__ out)
{
  extern __shared__ __align__(16) float sm[];
  __shared__ __align__(8) uint64_t mbar_s[3];
  const int tid = threadIdx.x, w = tid>>5, wm = w&3, wn = w>>2;
  const int vt = blockIdx.x, mt = blockIdx.y;
  const float* A0 = g_h1T[2*mt];
  const float* A1 = g_h1T[2*mt+1];

  wmma::fragment<wmma::accumulator,16,16,8,float> cf[4][4];
  #pragma unroll
  for (int i=0;i<4;i++)
    #pragma unroll
    for (int j=0;j<4;j++) wmma::fill_fragment(cf[i][j],0.f);

  const uint32_t smb = s2u(sm);
  const uint32_t mbb = s2u(mbar_s);
  if (tid==0){
    #pragma unroll
    for (int s=0;s<3;s++) mbar_init(mbb+8*s, 1u);
    asm volatile("fence.proxy.async.shared::cta;" ::: "memory");
  }
  __syncthreads();

  auto issue = [&](int c){
    const int s = c%3;
    const uint32_t mb = mbb + 8*s;
    mbar_expect(mb, 2*CHB + 18432);
    const uint32_t da = smb + (uint32_t)s*FC_STGF*4;
    bulk_ld(da,         A0 + c*CHF, CHB, mb);
    bulk_ld(da+CHB,     A1 + c*CHF, CHB, mb);
    bulk_ld(da+2*CHB,   g_WtF + (size_t)(vt*32 + c)*WFCF, 18432, mb);
  };
  if (tid==0){ for (int c=0;c<3;c++) issue(c); }

  for (int c=0;c<32;c++){
    mbar_wait(mbb + 8*(c%3), (uint32_t)((c/3)&1));
    const float* st = sm + (c%3)*FC_STGF;
    const float* b_s = st + 2*CHF;
    #pragma unroll
    for (int kk=0;kk<4;kk++){
      wmma::fragment<wmma::matrix_a,16,16,8,wmma::precision::tf32,wmma::col_major> af[4];
      #pragma unroll
      for (int i=0;i<4;i++){
        int m = wm*64 + i*16;
        const float* ab = (m>=128) ? (st+CHF) : st;
        wmma::load_matrix_sync(af[i], ab + kk*8*132 + (m&127), 132);
        #pragma unroll
        for (int e=0;e<af[i].num_elements;e++) af[i].x[e]=wmma::__float_to_tf32(af[i].x[e]);
      }
      #pragma unroll
      for (int j=0;j<4;j++){
        wmma::fragment<wmma::matrix_b,16,16,8,wmma::precision::tf32,wmma::col_major> bf;
        wmma::load_matrix_sync(bf, b_s + (wn*64 + j*16)*36 + kk*8, 36);
        #pragma unroll
        for (int e=0;e<bf.num_elements;e++) bf.x[e]=wmma::__float_to_tf32(bf.x[e]);
        #pragma unroll
        for (int i=0;i<4;i++) wmma::mma_sync(cf[i][j], af[i], bf, cf[i][j]);
      }
    }
    __syncthreads();
    if (tid==0 && c+3<32) issue(c+3);
  }

  float* stg = sm;
  #pragma unroll
  for (int h=0; h<2; h++){
    if (wn==h){
      #pragma unroll
      for (int i=0;i<4;i++)
        #pragma unroll
        for (int j=0;j<4;j++)
          wmma::store_matrix_sync(stg + (wm*64+i*16)*68 + j*16, cf[i][j], 68, wmma::mem_row_major);
    }
    __syncthreads();
    #pragma unroll
    for (int i=0;i<16;i++){
      int f = tid + i*256;
      int r = f>>4, c4 = f&15;
      int n = vt*128 + h*64 + c4*4;
      float4 v  = *(float4*)(stg + r*68 + c4*4);
      float4 bb = *(const float4*)(bfc + n);
      v.x+=bb.x; v.y+=bb.y; v.z+=bb.z; v.w+=bb.w;
      int b = r&127, t = 2*mt + (r>>7);
      __stcs((float4*)(out + ((size_t)b*Tt + t)*(size_t)Vv + n), v);
    }
    __syncthreads();
  }
}

// Final hidden states -> out tail [2, B, H] (de-transpose from chunked layout)
__global__ void states_kernel(float* __restrict__ out){
  int i = blockIdx.x*blockDim.x + threadIdx.x;
  if (i >= 2*BH) return;
  const size_t BTV = (size_t)Bsz*Tt*Vv;
  int layer = i >= BH;
  int j = i - layer*BH;
  int b = j>>10, n = j&1023;
  const float* src = layer ? g_h1T[Tt-1] : g_h0T[(Tt-1)&1];
  out[BTV + i] = src[(n>>5)*CHF + (n&31)*132 + b];
}

extern "C" void kernel_launch(void* const* d_in, const int* in_sizes, int n_in,
                              void* d_out, int out_size) {
  const float* x    = (const float*)d_in[0];
  const float* Wih0 = (const float*)d_in[1];
  const float* Whh0 = (const float*)d_in[2];
  const float* bih0 = (const float*)d_in[3];
  const float* bhh0 = (const float*)d_in[4];
  const float* Wih1 = (const float*)d_in[5];
  const float* Whh1 = (const float*)d_in[6];
  const float* bih1 = (const float*)d_in[7];
  const float* bhh1 = (const float*)d_in[8];
  const float* Wfc  = (const float*)d_in[9];
  const float* bfc  = (const float*)d_in[10];
  float* out = (float*)d_out;

  cudaFuncSetAttribute(rnn_persist, cudaFuncAttributeMaxDynamicSharedMemorySize, RP_SMEM);
  cudaFuncSetAttribute(fc2,         cudaFuncAttributeMaxDynamicSharedMemorySize, FC_SMEM);

  // 1) re-tile weights (tf32-rounded for recurrence) + transpose x
  pretile<<<4096, 256>>>(x, Whh0, Wih1, Whh1, Wfc);

  // 2) persistent recurrence: all 257 steps in ONE kernel, weights SMEM-resident,
  //    producer-warp bulk pipeline (no block syncs in the K loop)
  rnn_persist<<<NCTA, NTHR, RP_SMEM>>>(Wih0, bih0, bhh0, bih1, bhh1);

  // 3) batched trailing linear
  fc2<<<dim3(32,128), 256, FC_SMEM>>>(bfc, out);

  // 4) final states tail
  long long need = (long long)Bsz*Tt*Vv + 2LL*BH;
  if ((long long)out_size >= need)
    states_kernel<<<(2*BH + 255)/256, 256>>>(out);
}